// round 4
// baseline (speedup 1.0000x reference)
#include <cuda_runtime.h>
#include <math.h>

// Problem constants (fixed shapes for this problem instance)
#define D_MODEL 2048
#define BATCH   4
#define SEQLEN  4096
#define HEADS   16
#define DHEAD   128
#define MROWS   (BATCH * SEQLEN)      // 16384
#define NCHUNK  32
#define CLEN    (SEQLEN / NCHUNK)     // 128
#define EPS_F   1e-6f

// ---------------------------------------------------------------------------
// Scratch (device globals: no allocation allowed in kernel_launch)
// ---------------------------------------------------------------------------
__device__ float g_q[(size_t)MROWS * D_MODEL];
__device__ float g_k[(size_t)MROWS * D_MODEL];
__device__ float g_v[(size_t)MROWS * D_MODEL];
__device__ float g_attn[(size_t)MROWS * D_MODEL];
__device__ float g_sk[BATCH * HEADS * NCHUNK * DHEAD];
__device__ float g_skv[BATCH * HEADS * NCHUNK * DHEAD];

// ---------------------------------------------------------------------------
// SGEMM: C[M,N] = A[M,K] @ B[K,N] + bias, with fused epilogue
//   mode 0: plain (+bias)
//   mode 1: elu(x)+1                      (Q projection)
//   mode 2: (elu(x)+1) * mask[row]        (K projection)
//   mode 3: x * mask[row]                 (V projection)
// 128x128 block tile, K-tile 16, 256 threads, 8x8 per-thread register tile.
// All dims divisible (M=16384, N=K=2048), no bounds checks.
// ---------------------------------------------------------------------------
#define BM 128
#define BN 128
#define BK 16
#define TM 8
#define TN 8

__global__ __launch_bounds__(256, 2)
void sgemm_kernel(const float* __restrict__ A, const float* __restrict__ B,
                  const float* __restrict__ bias, const float* __restrict__ mask,
                  float* __restrict__ C, int M, int N, int K, int mode)
{
    __shared__ float As[BK][BM];   // A tile stored transposed
    __shared__ float Bs[BK][BN];

    const int tid  = threadIdx.x;
    const int bm   = blockIdx.y * BM;
    const int bn   = blockIdx.x * BN;

    const int tcol = tid % 16;     // 16 thread-cols
    const int trow = tid / 16;     // 16 thread-rows

    // A-tile load: BM x BK floats = 512 float4; 256 threads -> 2 each
    const int a_row = tid / 4;            // 0..63
    const int a_col = (tid % 4) * 4;      // 0,4,8,12
    // B-tile load: BK x BN floats = 512 float4; 2 each
    const int b_row = tid / 32;           // 0..7
    const int b_col = (tid % 32) * 4;     // 0..124

    float acc[TM][TN];
#pragma unroll
    for (int i = 0; i < TM; i++)
#pragma unroll
        for (int j = 0; j < TN; j++) acc[i][j] = 0.f;

    const float* Aptr = A + (size_t)bm * K;
    const float* Bptr = B + bn;

    for (int k0 = 0; k0 < K; k0 += BK) {
#pragma unroll
        for (int p = 0; p < 2; p++) {
            int r = a_row + p * 64;
            float4 va = *(const float4*)(Aptr + (size_t)r * K + k0 + a_col);
            As[a_col + 0][r] = va.x;
            As[a_col + 1][r] = va.y;
            As[a_col + 2][r] = va.z;
            As[a_col + 3][r] = va.w;
        }
#pragma unroll
        for (int p = 0; p < 2; p++) {
            int r = b_row + p * 8;
            float4 vb = *(const float4*)(Bptr + (size_t)(k0 + r) * N + b_col);
            *(float4*)&Bs[r][b_col] = vb;
        }
        __syncthreads();

#pragma unroll
        for (int kk = 0; kk < BK; kk++) {
            float ar[TM], br[TN];
            *(float4*)&ar[0] = *(const float4*)&As[kk][trow * TM];
            *(float4*)&ar[4] = *(const float4*)&As[kk][trow * TM + 4];
            *(float4*)&br[0] = *(const float4*)&Bs[kk][tcol * TN];
            *(float4*)&br[4] = *(const float4*)&Bs[kk][tcol * TN + 4];
#pragma unroll
            for (int i = 0; i < TM; i++)
#pragma unroll
                for (int j = 0; j < TN; j++)
                    acc[i][j] = fmaf(ar[i], br[j], acc[i][j]);
        }
        __syncthreads();
    }

    // Epilogue
#pragma unroll
    for (int i = 0; i < TM; i++) {
        const int row = bm + trow * TM + i;
        float mval = 1.f;
        if (mode == 2 || mode == 3) mval = mask[row];
#pragma unroll
        for (int j = 0; j < TN; j += 4) {
            const int col = bn + tcol * TN + j;
            float4 out;
            float* o = &out.x;
#pragma unroll
            for (int q = 0; q < 4; q++) {
                float vv = acc[i][j + q] + bias[col + q];
                if (mode == 1 || mode == 2)
                    vv = (vv > 0.f) ? (vv + 1.f) : __expf(vv);   // elu(x)+1
                if (mode == 2 || mode == 3)
                    vv *= mval;
                o[q] = vv;
            }
            *(float4*)(C + (size_t)row * N + col) = out;
        }
    }
}

// ---------------------------------------------------------------------------
// Phase 1: per-chunk sums of k and k*v (k, v already masked in GEMM epilogue)
// grid = B*H*NCHUNK blocks, 128 threads (one per head-dim channel)
// ---------------------------------------------------------------------------
__global__ __launch_bounds__(DHEAD)
void chunk_sums_kernel()
{
    const int unit = blockIdx.x;          // b*HEADS*NCHUNK + h*NCHUNK + c
    const int d    = threadIdx.x;
    const int c    = unit % NCHUNK;
    const int bh   = unit / NCHUNK;
    const int h    = bh % HEADS;
    const int b    = bh / HEADS;

    size_t base = ((size_t)(b * SEQLEN + c * CLEN)) * D_MODEL + h * DHEAD + d;
    float sk = 0.f, skv = 0.f;
#pragma unroll 4
    for (int i = 0; i < CLEN; i++) {
        float kk = g_k[base + (size_t)i * D_MODEL];
        float vv = g_v[base + (size_t)i * D_MODEL];
        sk  += kk;
        skv += kk * vv;
    }
    g_sk [(size_t)unit * DHEAD + d] = sk;
    g_skv[(size_t)unit * DHEAD + d] = skv;
}

// ---------------------------------------------------------------------------
// Phase 2: in-place exclusive prefix over chunks, per (b,h,d) channel
// ---------------------------------------------------------------------------
__global__ void chunk_prefix_kernel()
{
    const int idx = blockIdx.x * blockDim.x + threadIdx.x;
    if (idx >= BATCH * HEADS * DHEAD) return;
    const int d  = idx % DHEAD;
    const int bh = idx / DHEAD;

    size_t base = ((size_t)bh * NCHUNK) * DHEAD + d;
    float rk = 0.f, rkv = 0.f;
#pragma unroll
    for (int c = 0; c < NCHUNK; c++) {
        size_t p = base + (size_t)c * DHEAD;
        float tk = g_sk[p], tkv = g_skv[p];
        g_sk[p]  = rk;
        g_skv[p] = rkv;
        rk  += tk;
        rkv += tkv;
    }
}

// ---------------------------------------------------------------------------
// Phase 3: fused running cumsum + z reduction + normalized output
// grid = B*H*NCHUNK blocks, 128 threads (one per channel), block-reduce for z
// ---------------------------------------------------------------------------
__global__ __launch_bounds__(DHEAD)
void attn_out_kernel(const float* __restrict__ mask)
{
    const int unit = blockIdx.x;
    const int d    = threadIdx.x;
    const int lane = d & 31;
    const int warp = d >> 5;
    const int c    = unit % NCHUNK;
    const int bh   = unit / NCHUNK;
    const int h    = bh % HEADS;
    const int b    = bh / HEADS;

    __shared__ float wsum[4];

    float kc  = g_sk [(size_t)unit * DHEAD + d];
    float kvc = g_skv[(size_t)unit * DHEAD + d];

    const int l0 = c * CLEN;
    size_t base = ((size_t)(b * SEQLEN + l0)) * D_MODEL + h * DHEAD + d;

    for (int i = 0; i < CLEN; i++) {
        size_t p = base + (size_t)i * D_MODEL;
        float qq = g_q[p];
        float kk = g_k[p];
        float vv = g_v[p];
        kc  += kk;
        kvc += kk * vv;

        float s = qq * kc;
#pragma unroll
        for (int off = 16; off; off >>= 1)
            s += __shfl_xor_sync(0xffffffffu, s, off);
        if (lane == 0) wsum[warp] = s;
        __syncthreads();
        float z = (wsum[0] + wsum[1] + wsum[2] + wsum[3] + EPS_F)
                  * mask[b * SEQLEN + l0 + i];
        g_attn[p] = qq * kvc / z;
        __syncthreads();
    }
}

// ---------------------------------------------------------------------------
// Launch
// ---------------------------------------------------------------------------
extern "C" void kernel_launch(void* const* d_in, const int* in_sizes, int n_in,
                              void* d_out, int out_size)
{
    const float* x    = (const float*)d_in[0];
    const float* mask = (const float*)d_in[1];
    const float* Wq   = (const float*)d_in[2];
    const float* bq   = (const float*)d_in[3];
    const float* Wk   = (const float*)d_in[4];
    const float* bk   = (const float*)d_in[5];
    const float* Wv   = (const float*)d_in[6];
    const float* bv   = (const float*)d_in[7];
    const float* Wo   = (const float*)d_in[8];
    const float* bo   = (const float*)d_in[9];
    float* out = (float*)d_out;

    float *q, *k, *v, *attn;
    cudaGetSymbolAddress((void**)&q,    g_q);
    cudaGetSymbolAddress((void**)&k,    g_k);
    cudaGetSymbolAddress((void**)&v,    g_v);
    cudaGetSymbolAddress((void**)&attn, g_attn);

    dim3 grid(D_MODEL / BN, MROWS / BM);

    // Projections with fused bias + feature map + mask
    sgemm_kernel<<<grid, 256>>>(x, Wq, bq, nullptr, q,    MROWS, D_MODEL, D_MODEL, 1);
    sgemm_kernel<<<grid, 256>>>(x, Wk, bk, mask,    k,    MROWS, D_MODEL, D_MODEL, 2);
    sgemm_kernel<<<grid, 256>>>(x, Wv, bv, mask,    v,    MROWS, D_MODEL, D_MODEL, 3);

    // Linear-attention core (chunked scan)
    chunk_sums_kernel<<<BATCH * HEADS * NCHUNK, DHEAD>>>();
    chunk_prefix_kernel<<<(BATCH * HEADS * DHEAD + 255) / 256, 256>>>();
    attn_out_kernel<<<BATCH * HEADS * NCHUNK, DHEAD>>>(mask);

    // Output projection
    sgemm_kernel<<<grid, 256>>>(attn, Wo, bo, nullptr, out, MROWS, D_MODEL, D_MODEL, 0);
}

// round 7
// speedup vs baseline: 2.8395x; 2.8395x over previous
#include <cuda_runtime.h>
#include <cuda_bf16.h>
#include <math.h>
#include <stdint.h>

// Problem constants (fixed shapes)
#define D_MODEL 2048
#define BATCH   4
#define SEQLEN  4096
#define HEADS   16
#define DHEAD   128
#define MROWS   (BATCH * SEQLEN)      // 16384
#define NCHUNK  32
#define CLEN    (SEQLEN / NCHUNK)     // 128
#define EPS_F   1e-6f

// GEMM tiling (mma.sync m16n8k16 bf16, 3-product split)
#define BM 128
#define BN 128
#define BK 64                          // 64 bf16 = 128 B/row (one SW128 atom row)
#define KITERS  (D_MODEL / BK)         // 32
#define NSTAGE  3
#define GTHREADS 256                   // 8 warps: 2 (M) x 4 (N), warp tile 64x32

#define TILE_BYTES   (BM * 128)        // one bf16 tile: 128 rows x 128B = 16384
#define STAGE_BYTES  (4 * TILE_BYTES)  // A_hi, A_lo, B_hi, B_lo = 65536
#define SMEM_BYTES   (NSTAGE * STAGE_BYTES)   // 196608

// ---------------------------------------------------------------------------
// Scratch (device globals — no allocation allowed)
// ---------------------------------------------------------------------------
__device__ float g_q[(size_t)MROWS * D_MODEL];
__device__ float g_k[(size_t)MROWS * D_MODEL];
__device__ float g_v[(size_t)MROWS * D_MODEL];
__device__ float g_sk[BATCH * HEADS * NCHUNK * DHEAD];
__device__ float g_skv[BATCH * HEADS * NCHUNK * DHEAD];
__device__ __nv_bfloat16 g_xhi[(size_t)MROWS * D_MODEL];
__device__ __nv_bfloat16 g_xlo[(size_t)MROWS * D_MODEL];
__device__ __nv_bfloat16 g_ahi[(size_t)MROWS * D_MODEL];
__device__ __nv_bfloat16 g_alo[(size_t)MROWS * D_MODEL];
__device__ __nv_bfloat16 g_whi[4][(size_t)D_MODEL * D_MODEL];  // transposed [N,K]
__device__ __nv_bfloat16 g_wlo[4][(size_t)D_MODEL * D_MODEL];

// ---------------------------------------------------------------------------
// Helpers
// ---------------------------------------------------------------------------
__device__ __forceinline__ uint32_t smem_u32(const void* p) {
    uint32_t a;
    asm("{ .reg .u64 t; cvta.to.shared.u64 t, %1; cvt.u32.u64 %0, t; }" : "=r"(a) : "l"(p));
    return a;
}
// SW128 swizzle on byte offset (row stride 128B)
#define SWZ(x) ((x) ^ (((x) >> 3) & 0x70))

__device__ __forceinline__ void cp_async16(uint32_t dst, const void* src) {
    asm volatile("cp.async.cg.shared.global [%0], [%1], 16;\n" :: "r"(dst), "l"(src));
}
__device__ __forceinline__ void cp_commit() { asm volatile("cp.async.commit_group;\n" ::: "memory"); }
template <int N> __device__ __forceinline__ void cp_wait() {
    asm volatile("cp.async.wait_group %0;\n" :: "n"(N) : "memory");
}

#define MMA_BF16(acc, a, b) \
    asm volatile( \
        "mma.sync.aligned.m16n8k16.row.col.f32.bf16.bf16.f32 " \
        "{%0,%1,%2,%3}, {%4,%5,%6,%7}, {%8,%9}, {%0,%1,%2,%3};" \
        : "+f"((acc)[0]), "+f"((acc)[1]), "+f"((acc)[2]), "+f"((acc)[3]) \
        : "r"((a)[0]), "r"((a)[1]), "r"((a)[2]), "r"((a)[3]), \
          "r"((b)[0]), "r"((b)[1]))

// ---------------------------------------------------------------------------
// x split: fp32 -> (hi, lo) bf16, elementwise
// ---------------------------------------------------------------------------
__global__ __launch_bounds__(256)
void split_kernel(const float* __restrict__ S,
                  __nv_bfloat16* __restrict__ Hi, __nv_bfloat16* __restrict__ Lo,
                  int n4)
{
    int i = blockIdx.x * blockDim.x + threadIdx.x;
    if (i >= n4) return;
    float4 v = ((const float4*)S)[i];
    __nv_bfloat16 h0 = __float2bfloat16(v.x);
    __nv_bfloat16 h1 = __float2bfloat16(v.y);
    __nv_bfloat16 h2 = __float2bfloat16(v.z);
    __nv_bfloat16 h3 = __float2bfloat16(v.w);
    __nv_bfloat162 hA; hA.x = h0; hA.y = h1;
    __nv_bfloat162 hB; hB.x = h2; hB.y = h3;
    __nv_bfloat162 lA, lB;
    lA.x = __float2bfloat16(v.x - __bfloat162float(h0));
    lA.y = __float2bfloat16(v.y - __bfloat162float(h1));
    lB.x = __float2bfloat16(v.z - __bfloat162float(h2));
    lB.y = __float2bfloat16(v.w - __bfloat162float(h3));
    ((__nv_bfloat162*)Hi)[i * 2]     = hA;
    ((__nv_bfloat162*)Hi)[i * 2 + 1] = hB;
    ((__nv_bfloat162*)Lo)[i * 2]     = lA;
    ((__nv_bfloat162*)Lo)[i * 2 + 1] = lB;
}

// ---------------------------------------------------------------------------
// Weight transpose + split: W[k][n] fp32 -> Wt_hi/lo[n][k] bf16
// ---------------------------------------------------------------------------
__global__ __launch_bounds__(256)
void transpose_split_kernel(const float* __restrict__ S,
                            __nv_bfloat16* __restrict__ Hi,
                            __nv_bfloat16* __restrict__ Lo)
{
    __shared__ float t[32][33];
    const int tx = threadIdx.x, ty = threadIdx.y;   // 32x8
    int x = blockIdx.x * 32 + tx;
    int y = blockIdx.y * 32 + ty;
#pragma unroll
    for (int i = 0; i < 32; i += 8)
        t[ty + i][tx] = S[(size_t)(y + i) * D_MODEL + x];
    __syncthreads();
    x = blockIdx.y * 32 + tx;
    y = blockIdx.x * 32 + ty;
#pragma unroll
    for (int i = 0; i < 32; i += 8) {
        float v = t[tx][ty + i];
        __nv_bfloat16 h = __float2bfloat16(v);
        Hi[(size_t)(y + i) * D_MODEL + x] = h;
        Lo[(size_t)(y + i) * D_MODEL + x] = __float2bfloat16(v - __bfloat162float(h));
    }
}

// ---------------------------------------------------------------------------
// bf16x3 GEMM: C[M,N] = (Ahi+Alo)[M,K] @ (Bhi+Blo)[N,K]^T + bias, fused epi
//   mode 0: +bias
//   mode 1: elu(x+bias)+1
//   mode 2: (elu(x+bias)+1) * mask[row]
//   mode 3: (x+bias) * mask[row]
// grid = (N/BN, M/BM), 256 threads (8 warps 2x4, warp tile 64x32)
// ---------------------------------------------------------------------------
__global__ __launch_bounds__(GTHREADS)
void gemm_bf16x3_kernel(const __nv_bfloat16* __restrict__ Ahi,
                        const __nv_bfloat16* __restrict__ Alo,
                        const __nv_bfloat16* __restrict__ Bhi,
                        const __nv_bfloat16* __restrict__ Blo,
                        const float* __restrict__ bias, const float* __restrict__ mask,
                        float* __restrict__ C, int mode)
{
    extern __shared__ char smem[];
    const uint32_t smem_base = smem_u32(smem);
    const int tid  = threadIdx.x;
    const int wid  = tid >> 5;
    const int lane = tid & 31;
    const int wm   = wid >> 2;          // 0..1
    const int wn   = wid & 3;           // 0..3
    const int bm   = blockIdx.y * BM;
    const int bn   = blockIdx.x * BN;

    // ldmatrix addressing
    const int rx    = lane & 7;
    const int arow  = wm * 64 + (lane & 15);          // + mt*16
    const int asel  = lane >> 4;                      // k-chunk16 select
    const int brow  = wn * 32 + (lane & 7);           // + nt*8
    const int bsel  = (lane >> 3) & 1;

    // per-stage load: 4 tiles x 1024 chunks16 = 4096; 256 thr -> 16 each
    auto load_stage = [&](int st, int kit) {
        const int k0 = kit * BK;
        const uint32_t s0 = smem_base + st * STAGE_BYTES;
#pragma unroll
        for (int j = 0; j < 4; j++) {
            int idx = tid + j * GTHREADS;   // 0..1023
            int row = idx >> 3;
            int cc  = idx & 7;
            uint32_t off = SWZ(row * 128 + cc * 16);
            size_t gsrc = (size_t)(bm + row) * D_MODEL + k0 + cc * 8;
            cp_async16(s0 + off,                  Ahi + gsrc);
            cp_async16(s0 + TILE_BYTES + off,     Alo + gsrc);
        }
#pragma unroll
        for (int j = 0; j < 4; j++) {
            int idx = tid + j * GTHREADS;
            int row = idx >> 3;
            int cc  = idx & 7;
            uint32_t off = SWZ(row * 128 + cc * 16);
            size_t gsrc = (size_t)(bn + row) * D_MODEL + k0 + cc * 8;
            cp_async16(s0 + 2 * TILE_BYTES + off, Bhi + gsrc);
            cp_async16(s0 + 3 * TILE_BYTES + off, Blo + gsrc);
        }
    };

    float acc[4][4][4];
#pragma unroll
    for (int i = 0; i < 4; i++)
#pragma unroll
        for (int j = 0; j < 4; j++)
#pragma unroll
            for (int q = 0; q < 4; q++) acc[i][j][q] = 0.f;

    // prolog
#pragma unroll
    for (int s = 0; s < NSTAGE - 1; s++) { load_stage(s, s); cp_commit(); }

    for (int k = 0; k < KITERS; k++) {
        if (k + NSTAGE - 1 < KITERS)
            load_stage((k + NSTAGE - 1) % NSTAGE, k + NSTAGE - 1);
        cp_commit();
        cp_wait<NSTAGE - 1>();
        __syncthreads();

        const uint32_t sa  = smem_base + (k % NSTAGE) * STAGE_BYTES;
        const uint32_t sal = sa + TILE_BYTES;
        const uint32_t sbh = sa + 2 * TILE_BYTES;
        const uint32_t sbl = sa + 3 * TILE_BYTES;

#pragma unroll
        for (int ks = 0; ks < BK / 16; ks++) {          // 4 k-steps of 16
            const int ca = (((ks * 2 + asel) ^ rx) << 4);
            const int cb = (((ks * 2 + bsel) ^ rx) << 4);
            uint32_t afh[4][4], afl[4][4];
            uint32_t bfh[4][2], bfl[4][2];
#pragma unroll
            for (int mt = 0; mt < 4; mt++) {
                uint32_t roff = (uint32_t)((arow + mt * 16) * 128 + ca);
                asm volatile("ldmatrix.sync.aligned.m8n8.x4.shared.b16 {%0,%1,%2,%3}, [%4];"
                    : "=r"(afh[mt][0]), "=r"(afh[mt][1]), "=r"(afh[mt][2]), "=r"(afh[mt][3])
                    : "r"(sa + roff));
                asm volatile("ldmatrix.sync.aligned.m8n8.x4.shared.b16 {%0,%1,%2,%3}, [%4];"
                    : "=r"(afl[mt][0]), "=r"(afl[mt][1]), "=r"(afl[mt][2]), "=r"(afl[mt][3])
                    : "r"(sal + roff));
            }
#pragma unroll
            for (int nt = 0; nt < 4; nt++) {
                uint32_t roff = (uint32_t)((brow + nt * 8) * 128 + cb);
                asm volatile("ldmatrix.sync.aligned.m8n8.x2.shared.b16 {%0,%1}, [%2];"
                    : "=r"(bfh[nt][0]), "=r"(bfh[nt][1]) : "r"(sbh + roff));
                asm volatile("ldmatrix.sync.aligned.m8n8.x2.shared.b16 {%0,%1}, [%2];"
                    : "=r"(bfl[nt][0]), "=r"(bfl[nt][1]) : "r"(sbl + roff));
            }
#pragma unroll
            for (int mt = 0; mt < 4; mt++)
#pragma unroll
                for (int nt = 0; nt < 4; nt++) {
                    MMA_BF16(acc[mt][nt], afl[mt], bfh[nt]);   // lo*hi
                    MMA_BF16(acc[mt][nt], afh[mt], bfl[nt]);   // hi*lo
                    MMA_BF16(acc[mt][nt], afh[mt], bfh[nt]);   // hi*hi
                }
        }
        __syncthreads();
    }

    // Epilogue: c0,c1 -> (row0, col,col+1); c2,c3 -> (row0+8, ...)
    const int g  = lane >> 2;
    const int tg = lane & 3;
#pragma unroll
    for (int mt = 0; mt < 4; mt++) {
        const int row0 = bm + wm * 64 + mt * 16 + g;
        const int row1 = row0 + 8;
        float m0 = 1.f, m1 = 1.f;
        if (mode >= 2) { m0 = mask[row0]; m1 = mask[row1]; }
#pragma unroll
        for (int nt = 0; nt < 4; nt++) {
            const int col = bn + wn * 32 + nt * 8 + tg * 2;
            const float b0 = bias[col], b1 = bias[col + 1];
            float v00 = acc[mt][nt][0] + b0;
            float v01 = acc[mt][nt][1] + b1;
            float v10 = acc[mt][nt][2] + b0;
            float v11 = acc[mt][nt][3] + b1;
            if (mode == 1 || mode == 2) {
                v00 = (v00 > 0.f) ? (v00 + 1.f) : __expf(v00);
                v01 = (v01 > 0.f) ? (v01 + 1.f) : __expf(v01);
                v10 = (v10 > 0.f) ? (v10 + 1.f) : __expf(v10);
                v11 = (v11 > 0.f) ? (v11 + 1.f) : __expf(v11);
            }
            if (mode >= 2) { v00 *= m0; v01 *= m0; v10 *= m1; v11 *= m1; }
            *(float2*)(C + (size_t)row0 * D_MODEL + col) = make_float2(v00, v01);
            *(float2*)(C + (size_t)row1 * D_MODEL + col) = make_float2(v10, v11);
        }
    }
}

// ---------------------------------------------------------------------------
// Attention core
// ---------------------------------------------------------------------------
__global__ __launch_bounds__(DHEAD)
void chunk_sums_kernel()
{
    const int unit = blockIdx.x;
    const int d    = threadIdx.x;
    const int c    = unit % NCHUNK;
    const int bh   = unit / NCHUNK;
    const int h    = bh % HEADS;
    const int b    = bh / HEADS;

    size_t base = ((size_t)(b * SEQLEN + c * CLEN)) * D_MODEL + h * DHEAD + d;
    float sk = 0.f, skv = 0.f;
#pragma unroll 4
    for (int i = 0; i < CLEN; i++) {
        float kk = g_k[base + (size_t)i * D_MODEL];
        float vv = g_v[base + (size_t)i * D_MODEL];
        sk  += kk;
        skv += kk * vv;
    }
    g_sk [(size_t)unit * DHEAD + d] = sk;
    g_skv[(size_t)unit * DHEAD + d] = skv;
}

__global__ void chunk_prefix_kernel()
{
    const int idx = blockIdx.x * blockDim.x + threadIdx.x;
    if (idx >= BATCH * HEADS * DHEAD) return;
    const int d  = idx % DHEAD;
    const int bh = idx / DHEAD;

    size_t base = ((size_t)bh * NCHUNK) * DHEAD + d;
    float rk = 0.f, rkv = 0.f;
#pragma unroll
    for (int c = 0; c < NCHUNK; c++) {
        size_t p = base + (size_t)c * DHEAD;
        float tk = g_sk[p], tkv = g_skv[p];
        g_sk[p]  = rk;
        g_skv[p] = rkv;
        rk  += tk;
        rkv += tkv;
    }
}

// Phase 3: writes attn output directly as (hi, lo) bf16 split for the Wo GEMM
__global__ __launch_bounds__(DHEAD)
void attn_out_kernel(const float* __restrict__ mask)
{
    const int unit = blockIdx.x;
    const int d    = threadIdx.x;
    const int lane = d & 31;
    const int warp = d >> 5;
    const int c    = unit % NCHUNK;
    const int bh   = unit / NCHUNK;
    const int h    = bh % HEADS;
    const int b    = bh / HEADS;

    __shared__ float wsum[4];

    float kc  = g_sk [(size_t)unit * DHEAD + d];
    float kvc = g_skv[(size_t)unit * DHEAD + d];

    const int l0 = c * CLEN;
    size_t base = ((size_t)(b * SEQLEN + l0)) * D_MODEL + h * DHEAD + d;

    for (int i = 0; i < CLEN; i++) {
        size_t p = base + (size_t)i * D_MODEL;
        float qq = g_q[p];
        float kk = g_k[p];
        float vv = g_v[p];
        kc  += kk;
        kvc += kk * vv;

        float s = qq * kc;
#pragma unroll
        for (int off = 16; off; off >>= 1)
            s += __shfl_xor_sync(0xffffffffu, s, off);
        if (lane == 0) wsum[warp] = s;
        __syncthreads();
        float z = (wsum[0] + wsum[1] + wsum[2] + wsum[3] + EPS_F)
                  * mask[b * SEQLEN + l0 + i];
        float o = qq * kvc / z;
        __nv_bfloat16 hh = __float2bfloat16(o);
        g_ahi[p] = hh;
        g_alo[p] = __float2bfloat16(o - __bfloat162float(hh));
        __syncthreads();
    }
}

// ---------------------------------------------------------------------------
// Launch
// ---------------------------------------------------------------------------
extern "C" void kernel_launch(void* const* d_in, const int* in_sizes, int n_in,
                              void* d_out, int out_size)
{
    const float* x    = (const float*)d_in[0];
    const float* mask = (const float*)d_in[1];
    const float* Wq   = (const float*)d_in[2];
    const float* bq   = (const float*)d_in[3];
    const float* Wk   = (const float*)d_in[4];
    const float* bk   = (const float*)d_in[5];
    const float* Wv   = (const float*)d_in[6];
    const float* bv   = (const float*)d_in[7];
    const float* Wo   = (const float*)d_in[8];
    const float* bo   = (const float*)d_in[9];
    float* out = (float*)d_out;

    float *q, *k, *v;
    __nv_bfloat16 *xhi, *xlo, *ahi, *alo, *whi, *wlo;
    cudaGetSymbolAddress((void**)&q,   g_q);
    cudaGetSymbolAddress((void**)&k,   g_k);
    cudaGetSymbolAddress((void**)&v,   g_v);
    cudaGetSymbolAddress((void**)&xhi, g_xhi);
    cudaGetSymbolAddress((void**)&xlo, g_xlo);
    cudaGetSymbolAddress((void**)&ahi, g_ahi);
    cudaGetSymbolAddress((void**)&alo, g_alo);
    cudaGetSymbolAddress((void**)&whi, g_whi);
    cudaGetSymbolAddress((void**)&wlo, g_wlo);
    const size_t WSZ = (size_t)D_MODEL * D_MODEL;

    cudaFuncSetAttribute(gemm_bf16x3_kernel,
                         cudaFuncAttributeMaxDynamicSharedMemorySize, SMEM_BYTES);

    // Split x into bf16 hi/lo
    {
        int n4 = MROWS * D_MODEL / 4;
        split_kernel<<<(n4 + 255) / 256, 256>>>(x, xhi, xlo, n4);
    }
    // Transpose + split weights to [N,K] bf16 hi/lo
    dim3 tgrid(D_MODEL / 32, D_MODEL / 32), tblk(32, 8);
    transpose_split_kernel<<<tgrid, tblk>>>(Wq, whi + 0 * WSZ, wlo + 0 * WSZ);
    transpose_split_kernel<<<tgrid, tblk>>>(Wk, whi + 1 * WSZ, wlo + 1 * WSZ);
    transpose_split_kernel<<<tgrid, tblk>>>(Wv, whi + 2 * WSZ, wlo + 2 * WSZ);
    transpose_split_kernel<<<tgrid, tblk>>>(Wo, whi + 3 * WSZ, wlo + 3 * WSZ);

    dim3 ggrid(D_MODEL / BN, MROWS / BM);

    // Projections with fused bias + feature map + mask
    gemm_bf16x3_kernel<<<ggrid, GTHREADS, SMEM_BYTES>>>(xhi, xlo, whi + 0 * WSZ, wlo + 0 * WSZ, bq, nullptr, q, 1);
    gemm_bf16x3_kernel<<<ggrid, GTHREADS, SMEM_BYTES>>>(xhi, xlo, whi + 1 * WSZ, wlo + 1 * WSZ, bk, mask,    k, 2);
    gemm_bf16x3_kernel<<<ggrid, GTHREADS, SMEM_BYTES>>>(xhi, xlo, whi + 2 * WSZ, wlo + 2 * WSZ, bv, mask,    v, 3);

    // Linear-attention core (chunked scan); writes split attn directly
    chunk_sums_kernel<<<BATCH * HEADS * NCHUNK, DHEAD>>>();
    chunk_prefix_kernel<<<(BATCH * HEADS * DHEAD + 255) / 256, 256>>>();
    attn_out_kernel<<<BATCH * HEADS * NCHUNK, DHEAD>>>(mask);

    // Output projection
    gemm_bf16x3_kernel<<<ggrid, GTHREADS, SMEM_BYTES>>>(ahi, alo, whi + 3 * WSZ, wlo + 3 * WSZ, bo, nullptr, out, 0);
}

// round 8
// speedup vs baseline: 3.1262x; 1.1010x over previous
#include <cuda_runtime.h>
#include <cuda_bf16.h>
#include <math.h>
#include <stdint.h>

// Problem constants (fixed shapes)
#define D_MODEL 2048
#define BATCH   4
#define SEQLEN  4096
#define HEADS   16
#define DHEAD   128
#define MROWS   (BATCH * SEQLEN)      // 16384
#define NCHUNK  32
#define CLEN    (SEQLEN / NCHUNK)     // 128
#define EPS_F   1e-6f

// GEMM tiling (mma.sync m16n8k16 bf16, 3-product split)
#define BM 128
#define BN 256
#define BK 64                          // 64 bf16 = 128 B/row (one SW128 atom row)
#define KITERS  (D_MODEL / BK)         // 32
#define GTHREADS 512                   // 16 warps: 2 (M) x 8 (N), warp tile 64x32

#define A_TILE_BYTES (BM * 128)        // 16384 (per variant hi/lo)
#define B_TILE_BYTES (BN * 128)        // 32768 (per variant hi/lo)
#define STAGE_BYTES  (2 * A_TILE_BYTES + 2 * B_TILE_BYTES)   // 98304
#define SMEM_BYTES   (2 * STAGE_BYTES)                       // 196608, 2-stage

// stage-relative offsets
#define OFF_AHI 0
#define OFF_ALO (A_TILE_BYTES)
#define OFF_BHI (2 * A_TILE_BYTES)
#define OFF_BLO (2 * A_TILE_BYTES + B_TILE_BYTES)

// ---------------------------------------------------------------------------
// Scratch (device globals — no allocation allowed)
// ---------------------------------------------------------------------------
__device__ float g_q[(size_t)MROWS * D_MODEL];
__device__ float g_k[(size_t)MROWS * D_MODEL];
__device__ float g_v[(size_t)MROWS * D_MODEL];
__device__ float g_sk[BATCH * HEADS * NCHUNK * DHEAD];
__device__ float g_skv[BATCH * HEADS * NCHUNK * DHEAD];
__device__ __nv_bfloat16 g_xhi[(size_t)MROWS * D_MODEL];
__device__ __nv_bfloat16 g_xlo[(size_t)MROWS * D_MODEL];
__device__ __nv_bfloat16 g_ahi[(size_t)MROWS * D_MODEL];
__device__ __nv_bfloat16 g_alo[(size_t)MROWS * D_MODEL];
__device__ __nv_bfloat16 g_whi[4][(size_t)D_MODEL * D_MODEL];  // transposed [N,K]
__device__ __nv_bfloat16 g_wlo[4][(size_t)D_MODEL * D_MODEL];

// ---------------------------------------------------------------------------
// Helpers
// ---------------------------------------------------------------------------
__device__ __forceinline__ uint32_t smem_u32(const void* p) {
    uint32_t a;
    asm("{ .reg .u64 t; cvta.to.shared.u64 t, %1; cvt.u32.u64 %0, t; }" : "=r"(a) : "l"(p));
    return a;
}
// SW128 swizzle on byte offset (row stride 128B)
#define SWZ(x) ((x) ^ (((x) >> 3) & 0x70))

__device__ __forceinline__ void cp_async16(uint32_t dst, const void* src) {
    asm volatile("cp.async.cg.shared.global [%0], [%1], 16;\n" :: "r"(dst), "l"(src));
}
__device__ __forceinline__ void cp_commit() { asm volatile("cp.async.commit_group;\n" ::: "memory"); }
template <int N> __device__ __forceinline__ void cp_wait() {
    asm volatile("cp.async.wait_group %0;\n" :: "n"(N) : "memory");
}

#define MMA_BF16(acc, a, b) \
    asm volatile( \
        "mma.sync.aligned.m16n8k16.row.col.f32.bf16.bf16.f32 " \
        "{%0,%1,%2,%3}, {%4,%5,%6,%7}, {%8,%9}, {%0,%1,%2,%3};" \
        : "+f"((acc)[0]), "+f"((acc)[1]), "+f"((acc)[2]), "+f"((acc)[3]) \
        : "r"((a)[0]), "r"((a)[1]), "r"((a)[2]), "r"((a)[3]), \
          "r"((b)[0]), "r"((b)[1]))

// ---------------------------------------------------------------------------
// x split: fp32 -> (hi, lo) bf16, elementwise
// ---------------------------------------------------------------------------
__global__ __launch_bounds__(256)
void split_kernel(const float* __restrict__ S,
                  __nv_bfloat16* __restrict__ Hi, __nv_bfloat16* __restrict__ Lo,
                  int n4)
{
    int i = blockIdx.x * blockDim.x + threadIdx.x;
    if (i >= n4) return;
    float4 v = ((const float4*)S)[i];
    __nv_bfloat16 h0 = __float2bfloat16(v.x);
    __nv_bfloat16 h1 = __float2bfloat16(v.y);
    __nv_bfloat16 h2 = __float2bfloat16(v.z);
    __nv_bfloat16 h3 = __float2bfloat16(v.w);
    __nv_bfloat162 hA; hA.x = h0; hA.y = h1;
    __nv_bfloat162 hB; hB.x = h2; hB.y = h3;
    __nv_bfloat162 lA, lB;
    lA.x = __float2bfloat16(v.x - __bfloat162float(h0));
    lA.y = __float2bfloat16(v.y - __bfloat162float(h1));
    lB.x = __float2bfloat16(v.z - __bfloat162float(h2));
    lB.y = __float2bfloat16(v.w - __bfloat162float(h3));
    ((__nv_bfloat162*)Hi)[i * 2]     = hA;
    ((__nv_bfloat162*)Hi)[i * 2 + 1] = hB;
    ((__nv_bfloat162*)Lo)[i * 2]     = lA;
    ((__nv_bfloat162*)Lo)[i * 2 + 1] = lB;
}

// ---------------------------------------------------------------------------
// Weight transpose + split: W[k][n] fp32 -> Wt_hi/lo[n][k] bf16
// ---------------------------------------------------------------------------
__global__ __launch_bounds__(256)
void transpose_split_kernel(const float* __restrict__ S,
                            __nv_bfloat16* __restrict__ Hi,
                            __nv_bfloat16* __restrict__ Lo)
{
    __shared__ float t[32][33];
    const int tx = threadIdx.x, ty = threadIdx.y;   // 32x8
    int x = blockIdx.x * 32 + tx;
    int y = blockIdx.y * 32 + ty;
#pragma unroll
    for (int i = 0; i < 32; i += 8)
        t[ty + i][tx] = S[(size_t)(y + i) * D_MODEL + x];
    __syncthreads();
    x = blockIdx.y * 32 + tx;
    y = blockIdx.x * 32 + ty;
#pragma unroll
    for (int i = 0; i < 32; i += 8) {
        float v = t[tx][ty + i];
        __nv_bfloat16 h = __float2bfloat16(v);
        Hi[(size_t)(y + i) * D_MODEL + x] = h;
        Lo[(size_t)(y + i) * D_MODEL + x] = __float2bfloat16(v - __bfloat162float(h));
    }
}

// ---------------------------------------------------------------------------
// bf16x3 GEMM: C[M,N] = (Ahi+Alo)[M,K] @ (Bhi+Blo)[N,K]^T + bias, fused epi
//   mode 0: +bias ; 1: elu(x+bias)+1 ; 2: (elu+1)*mask ; 3: (x+bias)*mask
// grid = (N/BN, M/BM), 512 threads (16 warps 2x8, warp tile 64x32), 2-stage
// ---------------------------------------------------------------------------
__global__ __launch_bounds__(GTHREADS)
void gemm_bf16x3_kernel(const __nv_bfloat16* __restrict__ Ahi,
                        const __nv_bfloat16* __restrict__ Alo,
                        const __nv_bfloat16* __restrict__ Bhi,
                        const __nv_bfloat16* __restrict__ Blo,
                        const float* __restrict__ bias, const float* __restrict__ mask,
                        float* __restrict__ C, int mode)
{
    extern __shared__ char smem[];
    const uint32_t smem_base = smem_u32(smem);
    const int tid  = threadIdx.x;
    const int wid  = tid >> 5;
    const int lane = tid & 31;
    const int wm   = wid >> 3;          // 0..1
    const int wn   = wid & 7;           // 0..7
    const int bm   = blockIdx.y * BM;
    const int bn   = blockIdx.x * BN;

    // ldmatrix addressing (row&7 == lane&7 for all patterns below)
    const int rx    = lane & 7;
    const int arow  = wm * 64 + (lane & 15);                       // + mt*16
    const int asel  = lane >> 4;                                   // k-chunk16 sel
    const int brow  = wn * 32 + ((lane >> 4) & 1) * 8 + (lane & 7);// + p*16
    const int bsel  = (lane >> 3) & 1;

    // per-stage load: A 2x1024 chunks16, B 2x2048 chunks16; 512 thr
    auto load_stage = [&](int st, int kit) {
        const int k0 = kit * BK;
        const uint32_t s0 = smem_base + st * STAGE_BYTES;
#pragma unroll
        for (int j = 0; j < 2; j++) {
            int idx = tid + j * GTHREADS;   // 0..1023
            int row = idx >> 3;
            int cc  = idx & 7;
            uint32_t off = SWZ(row * 128 + cc * 16);
            size_t gsrc = (size_t)(bm + row) * D_MODEL + k0 + cc * 8;
            cp_async16(s0 + OFF_AHI + off, Ahi + gsrc);
            cp_async16(s0 + OFF_ALO + off, Alo + gsrc);
        }
#pragma unroll
        for (int j = 0; j < 4; j++) {
            int idx = tid + j * GTHREADS;   // 0..2047
            int row = idx >> 3;
            int cc  = idx & 7;
            uint32_t off = SWZ(row * 128 + cc * 16);
            size_t gsrc = (size_t)(bn + row) * D_MODEL + k0 + cc * 8;
            cp_async16(s0 + OFF_BHI + off, Bhi + gsrc);
            cp_async16(s0 + OFF_BLO + off, Blo + gsrc);
        }
    };

    float acc[4][4][4];
#pragma unroll
    for (int i = 0; i < 4; i++)
#pragma unroll
        for (int j = 0; j < 4; j++)
#pragma unroll
            for (int q = 0; q < 4; q++) acc[i][j][q] = 0.f;

    // prolog: stage 0
    load_stage(0, 0);
    cp_commit();

    for (int k = 0; k < KITERS; k++) {
        if (k + 1 < KITERS) load_stage((k + 1) & 1, k + 1);
        cp_commit();
        cp_wait<1>();
        __syncthreads();

        const uint32_t s0  = smem_base + (k & 1) * STAGE_BYTES;
        const uint32_t sah = s0 + OFF_AHI;
        const uint32_t sal = s0 + OFF_ALO;
        const uint32_t sbh = s0 + OFF_BHI;
        const uint32_t sbl = s0 + OFF_BLO;

#pragma unroll
        for (int ks = 0; ks < BK / 16; ks++) {          // 4 k-steps of 16
            const int ca = (((ks * 2 + asel) ^ rx) << 4);
            const int cb = (((ks * 2 + bsel) ^ rx) << 4);

            // B fragments for all 4 n8 tiles (2x ldmatrix.x4 per variant)
            uint32_t bfh[4][2], bfl[4][2];
#pragma unroll
            for (int p = 0; p < 2; p++) {
                uint32_t roff = (uint32_t)((brow + p * 16) * 128 + cb);
                asm volatile("ldmatrix.sync.aligned.m8n8.x4.shared.b16 {%0,%1,%2,%3}, [%4];"
                    : "=r"(bfh[p*2][0]), "=r"(bfh[p*2][1]),
                      "=r"(bfh[p*2+1][0]), "=r"(bfh[p*2+1][1])
                    : "r"(sbh + roff));
                asm volatile("ldmatrix.sync.aligned.m8n8.x4.shared.b16 {%0,%1,%2,%3}, [%4];"
                    : "=r"(bfl[p*2][0]), "=r"(bfl[p*2][1]),
                      "=r"(bfl[p*2+1][0]), "=r"(bfl[p*2+1][1])
                    : "r"(sbl + roff));
            }
#pragma unroll
            for (int mt = 0; mt < 4; mt++) {
                uint32_t afh[4], afl[4];
                uint32_t roff = (uint32_t)((arow + mt * 16) * 128 + ca);
                asm volatile("ldmatrix.sync.aligned.m8n8.x4.shared.b16 {%0,%1,%2,%3}, [%4];"
                    : "=r"(afh[0]), "=r"(afh[1]), "=r"(afh[2]), "=r"(afh[3])
                    : "r"(sah + roff));
                asm volatile("ldmatrix.sync.aligned.m8n8.x4.shared.b16 {%0,%1,%2,%3}, [%4];"
                    : "=r"(afl[0]), "=r"(afl[1]), "=r"(afl[2]), "=r"(afl[3])
                    : "r"(sal + roff));
#pragma unroll
                for (int nt = 0; nt < 4; nt++) {
                    MMA_BF16(acc[mt][nt], afl, bfh[nt]);   // lo*hi
                    MMA_BF16(acc[mt][nt], afh, bfl[nt]);   // hi*lo
                    MMA_BF16(acc[mt][nt], afh, bfh[nt]);   // hi*hi
                }
            }
        }
        __syncthreads();
    }

    // Epilogue: c0,c1 -> (row0, col,col+1); c2,c3 -> (row0+8, ...)
    const int g  = lane >> 2;
    const int tg = lane & 3;
#pragma unroll
    for (int mt = 0; mt < 4; mt++) {
        const int row0 = bm + wm * 64 + mt * 16 + g;
        const int row1 = row0 + 8;
        float m0 = 1.f, m1 = 1.f;
        if (mode >= 2) { m0 = mask[row0]; m1 = mask[row1]; }
#pragma unroll
        for (int nt = 0; nt < 4; nt++) {
            const int col = bn + wn * 32 + nt * 8 + tg * 2;
            const float b0 = bias[col], b1 = bias[col + 1];
            float v00 = acc[mt][nt][0] + b0;
            float v01 = acc[mt][nt][1] + b1;
            float v10 = acc[mt][nt][2] + b0;
            float v11 = acc[mt][nt][3] + b1;
            if (mode == 1 || mode == 2) {
                v00 = (v00 > 0.f) ? (v00 + 1.f) : __expf(v00);
                v01 = (v01 > 0.f) ? (v01 + 1.f) : __expf(v01);
                v10 = (v10 > 0.f) ? (v10 + 1.f) : __expf(v10);
                v11 = (v11 > 0.f) ? (v11 + 1.f) : __expf(v11);
            }
            if (mode >= 2) { v00 *= m0; v01 *= m0; v10 *= m1; v11 *= m1; }
            *(float2*)(C + (size_t)row0 * D_MODEL + col) = make_float2(v00, v01);
            *(float2*)(C + (size_t)row1 * D_MODEL + col) = make_float2(v10, v11);
        }
    }
}

// ---------------------------------------------------------------------------
// Attention core
// ---------------------------------------------------------------------------
__global__ __launch_bounds__(DHEAD)
void chunk_sums_kernel()
{
    const int unit = blockIdx.x;
    const int d    = threadIdx.x;
    const int c    = unit % NCHUNK;
    const int bh   = unit / NCHUNK;
    const int h    = bh % HEADS;
    const int b    = bh / HEADS;

    size_t base = ((size_t)(b * SEQLEN + c * CLEN)) * D_MODEL + h * DHEAD + d;
    float sk = 0.f, skv = 0.f;
#pragma unroll 4
    for (int i = 0; i < CLEN; i++) {
        float kk = g_k[base + (size_t)i * D_MODEL];
        float vv = g_v[base + (size_t)i * D_MODEL];
        sk  += kk;
        skv += kk * vv;
    }
    g_sk [(size_t)unit * DHEAD + d] = sk;
    g_skv[(size_t)unit * DHEAD + d] = skv;
}

__global__ void chunk_prefix_kernel()
{
    const int idx = blockIdx.x * blockDim.x + threadIdx.x;
    if (idx >= BATCH * HEADS * DHEAD) return;
    const int d  = idx % DHEAD;
    const int bh = idx / DHEAD;

    size_t base = ((size_t)bh * NCHUNK) * DHEAD + d;
    float rk = 0.f, rkv = 0.f;
#pragma unroll
    for (int c = 0; c < NCHUNK; c++) {
        size_t p = base + (size_t)c * DHEAD;
        float tk = g_sk[p], tkv = g_skv[p];
        g_sk[p]  = rk;
        g_skv[p] = rkv;
        rk  += tk;
        rkv += tkv;
    }
}

// Phase 3: writes attn output directly as (hi, lo) bf16 split for the Wo GEMM
__global__ __launch_bounds__(DHEAD)
void attn_out_kernel(const float* __restrict__ mask)
{
    const int unit = blockIdx.x;
    const int d    = threadIdx.x;
    const int lane = d & 31;
    const int warp = d >> 5;
    const int c    = unit % NCHUNK;
    const int bh   = unit / NCHUNK;
    const int h    = bh % HEADS;
    const int b    = bh / HEADS;

    __shared__ float wsum[4];

    float kc  = g_sk [(size_t)unit * DHEAD + d];
    float kvc = g_skv[(size_t)unit * DHEAD + d];

    const int l0 = c * CLEN;
    size_t base = ((size_t)(b * SEQLEN + l0)) * D_MODEL + h * DHEAD + d;

    for (int i = 0; i < CLEN; i++) {
        size_t p = base + (size_t)i * D_MODEL;
        float qq = g_q[p];
        float kk = g_k[p];
        float vv = g_v[p];
        kc  += kk;
        kvc += kk * vv;

        float s = qq * kc;
#pragma unroll
        for (int off = 16; off; off >>= 1)
            s += __shfl_xor_sync(0xffffffffu, s, off);
        if (lane == 0) wsum[warp] = s;
        __syncthreads();
        float z = (wsum[0] + wsum[1] + wsum[2] + wsum[3] + EPS_F)
                  * mask[b * SEQLEN + l0 + i];
        float o = qq * kvc / z;
        __nv_bfloat16 hh = __float2bfloat16(o);
        g_ahi[p] = hh;
        g_alo[p] = __float2bfloat16(o - __bfloat162float(hh));
        __syncthreads();
    }
}

// ---------------------------------------------------------------------------
// Launch
// ---------------------------------------------------------------------------
extern "C" void kernel_launch(void* const* d_in, const int* in_sizes, int n_in,
                              void* d_out, int out_size)
{
    const float* x    = (const float*)d_in[0];
    const float* mask = (const float*)d_in[1];
    const float* Wq   = (const float*)d_in[2];
    const float* bq   = (const float*)d_in[3];
    const float* Wk   = (const float*)d_in[4];
    const float* bk   = (const float*)d_in[5];
    const float* Wv   = (const float*)d_in[6];
    const float* bv   = (const float*)d_in[7];
    const float* Wo   = (const float*)d_in[8];
    const float* bo   = (const float*)d_in[9];
    float* out = (float*)d_out;

    float *q, *k, *v;
    __nv_bfloat16 *xhi, *xlo, *ahi, *alo, *whi, *wlo;
    cudaGetSymbolAddress((void**)&q,   g_q);
    cudaGetSymbolAddress((void**)&k,   g_k);
    cudaGetSymbolAddress((void**)&v,   g_v);
    cudaGetSymbolAddress((void**)&xhi, g_xhi);
    cudaGetSymbolAddress((void**)&xlo, g_xlo);
    cudaGetSymbolAddress((void**)&ahi, g_ahi);
    cudaGetSymbolAddress((void**)&alo, g_alo);
    cudaGetSymbolAddress((void**)&whi, g_whi);
    cudaGetSymbolAddress((void**)&wlo, g_wlo);
    const size_t WSZ = (size_t)D_MODEL * D_MODEL;

    cudaFuncSetAttribute(gemm_bf16x3_kernel,
                         cudaFuncAttributeMaxDynamicSharedMemorySize, SMEM_BYTES);

    // Split x into bf16 hi/lo
    {
        int n4 = MROWS * D_MODEL / 4;
        split_kernel<<<(n4 + 255) / 256, 256>>>(x, xhi, xlo, n4);
    }
    // Transpose + split weights to [N,K] bf16 hi/lo
    dim3 tgrid(D_MODEL / 32, D_MODEL / 32), tblk(32, 8);
    transpose_split_kernel<<<tgrid, tblk>>>(Wq, whi + 0 * WSZ, wlo + 0 * WSZ);
    transpose_split_kernel<<<tgrid, tblk>>>(Wk, whi + 1 * WSZ, wlo + 1 * WSZ);
    transpose_split_kernel<<<tgrid, tblk>>>(Wv, whi + 2 * WSZ, wlo + 2 * WSZ);
    transpose_split_kernel<<<tgrid, tblk>>>(Wo, whi + 3 * WSZ, wlo + 3 * WSZ);

    dim3 ggrid(D_MODEL / BN, MROWS / BM);

    // Projections with fused bias + feature map + mask
    gemm_bf16x3_kernel<<<ggrid, GTHREADS, SMEM_BYTES>>>(xhi, xlo, whi + 0 * WSZ, wlo + 0 * WSZ, bq, nullptr, q, 1);
    gemm_bf16x3_kernel<<<ggrid, GTHREADS, SMEM_BYTES>>>(xhi, xlo, whi + 1 * WSZ, wlo + 1 * WSZ, bk, mask,    k, 2);
    gemm_bf16x3_kernel<<<ggrid, GTHREADS, SMEM_BYTES>>>(xhi, xlo, whi + 2 * WSZ, wlo + 2 * WSZ, bv, mask,    v, 3);

    // Linear-attention core (chunked scan); writes split attn directly
    chunk_sums_kernel<<<BATCH * HEADS * NCHUNK, DHEAD>>>();
    chunk_prefix_kernel<<<(BATCH * HEADS * DHEAD + 255) / 256, 256>>>();
    attn_out_kernel<<<BATCH * HEADS * NCHUNK, DHEAD>>>(mask);

    // Output projection
    gemm_bf16x3_kernel<<<ggrid, GTHREADS, SMEM_BYTES>>>(ahi, alo, whi + 3 * WSZ, wlo + 3 * WSZ, bo, nullptr, out, 0);
}